// round 3
// baseline (speedup 1.0000x reference)
#include <cuda_runtime.h>
#include <math.h>

#define N_NODES 131072
#define NNZV (N_NODES * 16)

// ---- scratch (no allocation allowed) ----
__device__ float d_xw[N_NODES * 32];   // x @ W1
__device__ float d_g [N_NODES * 32];   // spmm accumulator (zeroed each pass)
__device__ float d_h1[N_NODES * 32];   // relu(spmm1 + b1)
__device__ float d_h2[N_NODES * 64];   // relu(spmm2 @ W2 + b2)

typedef unsigned long long u64;

// ---- packed f32x2 helpers (Blackwell FFMA2) ----
static __device__ __forceinline__ u64 pk(float a, float b) {
    u64 r; asm("mov.b64 %0,{%1,%2};" : "=l"(r) : "f"(a), "f"(b)); return r;
}
static __device__ __forceinline__ u64 pk1(float a) { return pk(a, a); }
static __device__ __forceinline__ void upk(u64 v, float& a, float& b) {
    asm("mov.b64 {%0,%1},%2;" : "=f"(a), "=f"(b) : "l"(v));
}
static __device__ __forceinline__ u64 f2(u64 a, u64 b, u64 c) {
    u64 d; asm("fma.rn.f32x2 %0,%1,%2,%3;" : "=l"(d) : "l"(a), "l"(b), "l"(c)); return d;
}
static __device__ __forceinline__ u64 m2(u64 a, u64 b) {
    u64 d; asm("mul.rn.f32x2 %0,%1,%2;" : "=l"(d) : "l"(a), "l"(b)); return d;
}

// =====================================================================
// K1: xw = x @ W1  [N,128]@[128,32], and zero the spmm accumulator d_g
// =====================================================================
__global__ __launch_bounds__(256) void k1_xw(const float* __restrict__ x,
                                             const float* __restrict__ W1) {
    extern __shared__ float sx[];  // [256][129] padded
    const int t = threadIdx.x;
    const size_t xbase = (size_t)blockIdx.x * 256 * 128;
    const size_t gbase = (size_t)blockIdx.x * 256 * 32;

    for (int i = t; i < 256 * 128; i += 256)
        sx[(i >> 7) * 129 + (i & 127)] = x[xbase + i];
    for (int i = t; i < 256 * 32; i += 256)
        d_g[gbase + i] = 0.f;
    __syncthreads();

    u64 acc[16];
#pragma unroll
    for (int i = 0; i < 16; i++) acc[i] = 0ULL;
    const float* xr = &sx[t * 129];
#pragma unroll 4
    for (int k = 0; k < 128; k++) {
        u64 xx = pk1(xr[k]);
        const float4* w = (const float4*)(W1 + k * 32);
#pragma unroll
        for (int j = 0; j < 8; j++) {
            float4 wv = __ldg(w + j);
            acc[2 * j]     = f2(xx, pk(wv.x, wv.y), acc[2 * j]);
            acc[2 * j + 1] = f2(xx, pk(wv.z, wv.w), acc[2 * j + 1]);
        }
    }
    float* orow = &d_xw[gbase + t * 32];
#pragma unroll
    for (int j = 0; j < 8; j++) {
        float a, b, c, d;
        upk(acc[2 * j], a, b); upk(acc[2 * j + 1], c, d);
        *(float4*)(orow + 4 * j) = make_float4(a, b, c, d);
    }
}

// =====================================================================
// SpMM: d_g[row] += val * src[col]  (32 features, 8 lanes/edge, v4 RED)
// =====================================================================
__global__ __launch_bounds__(256) void k_spmm(const float4* __restrict__ src,
                                              const int* __restrict__ rows,
                                              const int* __restrict__ cols,
                                              const float* __restrict__ vals,
                                              float4* __restrict__ dst) {
    const int gid = blockIdx.x * 256 + threadIdx.x;
    const int e = gid >> 3, sub = gid & 7;
    const int r = __ldg(rows + e);
    const int c = __ldg(cols + e);
    const float v = __ldg(vals + e);
    float4 s = __ldg(src + (size_t)c * 8 + sub);
    float4* p = dst + (size_t)r * 8 + sub;
    asm volatile("red.global.add.v4.f32 [%0], {%1,%2,%3,%4};"
                 :: "l"(p), "f"(v * s.x), "f"(v * s.y), "f"(v * s.z), "f"(v * s.w)
                 : "memory");
}

// =====================================================================
// K3: h1 = relu(g + b1); g = 0 (ready for spmm2)
// =====================================================================
__global__ __launch_bounds__(256) void k_relu(const float* __restrict__ b1) {
    const int i = blockIdx.x * 256 + threadIdx.x;  // float4 index
    float4 g = ((const float4*)d_g)[i];
    float4 bb = __ldg(((const float4*)b1) + (i & 7));
    float4 h;
    h.x = fmaxf(g.x + bb.x, 0.f);
    h.y = fmaxf(g.y + bb.y, 0.f);
    h.z = fmaxf(g.z + bb.z, 0.f);
    h.w = fmaxf(g.w + bb.w, 0.f);
    ((float4*)d_h1)[i] = h;
    ((float4*)d_g)[i] = make_float4(0.f, 0.f, 0.f, 0.f);
}

// =====================================================================
// K5: h2 = relu(g @ W2 + b2)  [N,32]@[32,64]
// =====================================================================
__global__ __launch_bounds__(256) void k5_h2(const float* __restrict__ W2,
                                             const float* __restrict__ b2) {
    __shared__ float sg[256 * 33];
    const int t = threadIdx.x;
    const size_t base = (size_t)blockIdx.x * 256 * 32;
    for (int i = t; i < 256 * 32; i += 256)
        sg[(i >> 5) * 33 + (i & 31)] = d_g[base + i];
    __syncthreads();

    u64 acc[32];
#pragma unroll
    for (int i = 0; i < 32; i++) acc[i] = pk(__ldg(b2 + 2 * i), __ldg(b2 + 2 * i + 1));
    const float* gr = &sg[t * 33];
#pragma unroll 2
    for (int k = 0; k < 32; k++) {
        u64 gg = pk1(gr[k]);
        const float4* w = (const float4*)(W2 + k * 64);
#pragma unroll
        for (int j = 0; j < 16; j++) {
            float4 wv = __ldg(w + j);
            acc[2 * j]     = f2(gg, pk(wv.x, wv.y), acc[2 * j]);
            acc[2 * j + 1] = f2(gg, pk(wv.z, wv.w), acc[2 * j + 1]);
        }
    }
    float* orow = &d_h2[(size_t)blockIdx.x * 256 * 64 + t * 64];
#pragma unroll
    for (int j = 0; j < 16; j++) {
        float a, b, c, d;
        upk(acc[2 * j], a, b); upk(acc[2 * j + 1], c, d);
        *(float4*)(orow + 4 * j) = make_float4(fmaxf(a, 0.f), fmaxf(b, 0.f),
                                               fmaxf(c, 0.f), fmaxf(d, 0.f));
    }
}

// =====================================================================
// K6: per-256-block transformer encoder layer + classifier + log_softmax
// One CTA per block, thread t owns row t.
// =====================================================================
#define SP 68   // smem row pad (float4-aligned)
#define FFP 131 // ffn g-stash pad (conflict-free scalar)

__global__ __launch_bounds__(256, 1) void k6_enc(
    const float* __restrict__ Wqkv, const float* __restrict__ bqkv,
    const float* __restrict__ Wo,   const float* __restrict__ bo,
    const float* __restrict__ lg1,  const float* __restrict__ lb1,
    const float* __restrict__ Wf1,  const float* __restrict__ bf1,
    const float* __restrict__ Wf2,  const float* __restrict__ bf2,
    const float* __restrict__ lg2,  const float* __restrict__ lb2,
    const float* __restrict__ Wc,   const float* __restrict__ bc,
    float* __restrict__ out) {
    extern __shared__ float smbuf[];
    float* sk = smbuf;
    float* sv = smbuf + 256 * SP;
    const int t = threadIdx.x;
    const float* hblk = d_h2 + (size_t)blockIdx.x * 256 * 64;

    // stage h block, then own row -> regs
    for (int i = t; i < 256 * 64; i += 256)
        sk[(i >> 6) * SP + (i & 63)] = hblk[i];
    __syncthreads();
    float hreg[64];
#pragma unroll
    for (int i = 0; i < 16; i++) {
        float4 v = *(const float4*)&sk[t * SP + 4 * i];
        hreg[4 * i] = v.x; hreg[4 * i + 1] = v.y; hreg[4 * i + 2] = v.z; hreg[4 * i + 3] = v.w;
    }

    // ---- QKV: q -> regs, k/v -> smem (own-row writes, no race) ----
    float qv[64];
#pragma unroll
    for (int jt = 0; jt < 12; jt++) {
        const int j0 = jt * 16;
        u64 acc[8];
#pragma unroll
        for (int i = 0; i < 8; i++)
            acc[i] = pk(__ldg(bqkv + j0 + 2 * i), __ldg(bqkv + j0 + 2 * i + 1));
#pragma unroll 2
        for (int k = 0; k < 64; k++) {
            u64 hh = pk1(hreg[k]);
            const float4* w = (const float4*)(Wqkv + k * 192 + j0);
            float4 w0 = __ldg(w), w1 = __ldg(w + 1), w2 = __ldg(w + 2), w3 = __ldg(w + 3);
            acc[0] = f2(hh, pk(w0.x, w0.y), acc[0]); acc[1] = f2(hh, pk(w0.z, w0.w), acc[1]);
            acc[2] = f2(hh, pk(w1.x, w1.y), acc[2]); acc[3] = f2(hh, pk(w1.z, w1.w), acc[3]);
            acc[4] = f2(hh, pk(w2.x, w2.y), acc[4]); acc[5] = f2(hh, pk(w2.z, w2.w), acc[5]);
            acc[6] = f2(hh, pk(w3.x, w3.y), acc[6]); acc[7] = f2(hh, pk(w3.z, w3.w), acc[7]);
        }
        float o[16];
#pragma unroll
        for (int i = 0; i < 8; i++) upk(acc[i], o[2 * i], o[2 * i + 1]);
        if (jt < 4) {
#pragma unroll
            for (int i = 0; i < 16; i++) qv[j0 + i] = o[i];
        } else if (jt < 8) {
            float* kr = &sk[t * SP + (j0 - 64)];
#pragma unroll
            for (int i = 0; i < 16; i++) kr[i] = o[i];
        } else {
            float* vr = &sv[t * SP + (j0 - 128)];
#pragma unroll
            for (int i = 0; i < 16; i++) vr[i] = o[i];
        }
    }
    __syncthreads();

    // ---- attention: online softmax per head ----
    float ctx[64];
#pragma unroll
    for (int h = 0; h < 4; h++) {
        u64 qp[8];
#pragma unroll
        for (int i = 0; i < 8; i++) qp[i] = pk(qv[h * 16 + 2 * i], qv[h * 16 + 2 * i + 1]);
        float mx = -1e30f, l = 0.f;
        u64 av[8];
#pragma unroll
        for (int i = 0; i < 8; i++) av[i] = 0ULL;
        for (int kk = 0; kk < 256; kk++) {
            const float* kr = &sk[kk * SP + h * 16];
            float4 k0 = *(const float4*)kr,      k1 = *(const float4*)(kr + 4);
            float4 k2 = *(const float4*)(kr + 8), k3 = *(const float4*)(kr + 12);
            u64 da = 0ULL, db = 0ULL;
            da = f2(qp[0], pk(k0.x, k0.y), da); db = f2(qp[1], pk(k0.z, k0.w), db);
            da = f2(qp[2], pk(k1.x, k1.y), da); db = f2(qp[3], pk(k1.z, k1.w), db);
            da = f2(qp[4], pk(k2.x, k2.y), da); db = f2(qp[5], pk(k2.z, k2.w), db);
            da = f2(qp[6], pk(k3.x, k3.y), da); db = f2(qp[7], pk(k3.z, k3.w), db);
            float a0, a1, b0, b1;
            upk(da, a0, a1); upk(db, b0, b1);
            float s = ((a0 + a1) + (b0 + b1)) * 0.25f;
            if (s > mx) {
                float c = __expf(mx - s); mx = s; l *= c;
                u64 cp = pk1(c);
#pragma unroll
                for (int i = 0; i < 8; i++) av[i] = m2(av[i], cp);
            }
            float p = __expf(s - mx); l += p;
            u64 pp = pk1(p);
            const float* vr = &sv[kk * SP + h * 16];
            float4 v0 = *(const float4*)vr,      v1 = *(const float4*)(vr + 4);
            float4 v2 = *(const float4*)(vr + 8), v3 = *(const float4*)(vr + 12);
            av[0] = f2(pp, pk(v0.x, v0.y), av[0]); av[1] = f2(pp, pk(v0.z, v0.w), av[1]);
            av[2] = f2(pp, pk(v1.x, v1.y), av[2]); av[3] = f2(pp, pk(v1.z, v1.w), av[3]);
            av[4] = f2(pp, pk(v2.x, v2.y), av[4]); av[5] = f2(pp, pk(v2.z, v2.w), av[5]);
            av[6] = f2(pp, pk(v3.x, v3.y), av[6]); av[7] = f2(pp, pk(v3.z, v3.w), av[7]);
        }
        float invl = 1.f / l;
#pragma unroll
        for (int i = 0; i < 8; i++) {
            float lo, hi; upk(av[i], lo, hi);
            ctx[h * 16 + 2 * i] = lo * invl; ctx[h * 16 + 2 * i + 1] = hi * invl;
        }
    }

    // ---- Wo + residual -> x1 ----
    float x1[64];
#pragma unroll
    for (int jt = 0; jt < 4; jt++) {
        const int j0 = jt * 16;
        u64 acc[8];
#pragma unroll
        for (int i = 0; i < 8; i++)
            acc[i] = pk(__ldg(bo + j0 + 2 * i), __ldg(bo + j0 + 2 * i + 1));
#pragma unroll 2
        for (int k = 0; k < 64; k++) {
            u64 cc = pk1(ctx[k]);
            const float4* w = (const float4*)(Wo + k * 64 + j0);
            float4 w0 = __ldg(w), w1 = __ldg(w + 1), w2 = __ldg(w + 2), w3 = __ldg(w + 3);
            acc[0] = f2(cc, pk(w0.x, w0.y), acc[0]); acc[1] = f2(cc, pk(w0.z, w0.w), acc[1]);
            acc[2] = f2(cc, pk(w1.x, w1.y), acc[2]); acc[3] = f2(cc, pk(w1.z, w1.w), acc[3]);
            acc[4] = f2(cc, pk(w2.x, w2.y), acc[4]); acc[5] = f2(cc, pk(w2.z, w2.w), acc[5]);
            acc[6] = f2(cc, pk(w3.x, w3.y), acc[6]); acc[7] = f2(cc, pk(w3.z, w3.w), acc[7]);
        }
        const float4* hr = (const float4*)(hblk + (size_t)t * 64 + j0);
        float4 r0 = __ldg(hr), r1 = __ldg(hr + 1), r2 = __ldg(hr + 2), r3 = __ldg(hr + 3);
        float rr[16] = { r0.x, r0.y, r0.z, r0.w, r1.x, r1.y, r1.z, r1.w,
                         r2.x, r2.y, r2.z, r2.w, r3.x, r3.y, r3.z, r3.w };
#pragma unroll
        for (int i = 0; i < 8; i++) {
            float lo, hi; upk(acc[i], lo, hi);
            x1[j0 + 2 * i] = lo + rr[2 * i]; x1[j0 + 2 * i + 1] = hi + rr[2 * i + 1];
        }
    }

    // ---- LN1 ----
    float mu = 0.f;
#pragma unroll
    for (int j = 0; j < 64; j++) mu += x1[j];
    mu *= (1.f / 64.f);
    float var = 0.f;
#pragma unroll
    for (int j = 0; j < 64; j++) { float d = x1[j] - mu; var += d * d; }
    var *= (1.f / 64.f);
    float rs = rsqrtf(var + 1e-5f);
    float xn[64];
#pragma unroll
    for (int j = 0; j < 64; j++)
        xn[j] = (x1[j] - mu) * rs * __ldg(lg1 + j) + __ldg(lb1 + j);

    // ---- FFN phase 1: g = gelu(xn @ Wf1 + bf1) -> smem stash ----
    __syncthreads();  // all CTAs done with sk/sv
    float* gsh = smbuf;  // [256][FFP]
#pragma unroll
    for (int mc = 0; mc < 4; mc++) {
        const int m0 = mc * 32;
        u64 ga[16];
#pragma unroll
        for (int i = 0; i < 16; i++)
            ga[i] = pk(__ldg(bf1 + m0 + 2 * i), __ldg(bf1 + m0 + 2 * i + 1));
#pragma unroll 2
        for (int k = 0; k < 64; k++) {
            u64 xx = pk1(xn[k]);
            const float4* w = (const float4*)(Wf1 + k * 128 + m0);
#pragma unroll
            for (int j = 0; j < 8; j++) {
                float4 wv = __ldg(w + j);
                ga[2 * j]     = f2(xx, pk(wv.x, wv.y), ga[2 * j]);
                ga[2 * j + 1] = f2(xx, pk(wv.z, wv.w), ga[2 * j + 1]);
            }
        }
#pragma unroll
        for (int i = 0; i < 16; i++) {
            float a, b; upk(ga[i], a, b);
            gsh[t * FFP + m0 + 2 * i]     = 0.5f * a * (1.f + erff(a * 0.70710678118654752f));
            gsh[t * FFP + m0 + 2 * i + 1] = 0.5f * b * (1.f + erff(b * 0.70710678118654752f));
        }
    }

    // ---- FFN phase 2: ff = g @ Wf2 + bf2 (rolled, own-row smem reads) ----
    u64 fa[32];
#pragma unroll
    for (int i = 0; i < 32; i++) fa[i] = pk(__ldg(bf2 + 2 * i), __ldg(bf2 + 2 * i + 1));
    for (int mm = 0; mm < 128; mm++) {
        u64 gg = pk1(gsh[t * FFP + mm]);
        const float4* w = (const float4*)(Wf2 + mm * 64);
#pragma unroll
        for (int j = 0; j < 16; j++) {
            float4 wv = __ldg(w + j);
            fa[2 * j]     = f2(gg, pk(wv.x, wv.y), fa[2 * j]);
            fa[2 * j + 1] = f2(gg, pk(wv.z, wv.w), fa[2 * j + 1]);
        }
    }

    // ---- residual + LN2 ----
    float x2[64];
#pragma unroll
    for (int i = 0; i < 32; i++) {
        float lo, hi; upk(fa[i], lo, hi);
        x2[2 * i] = xn[2 * i] + lo; x2[2 * i + 1] = xn[2 * i + 1] + hi;
    }
    mu = 0.f;
#pragma unroll
    for (int j = 0; j < 64; j++) mu += x2[j];
    mu *= (1.f / 64.f);
    var = 0.f;
#pragma unroll
    for (int j = 0; j < 64; j++) { float d = x2[j] - mu; var += d * d; }
    var *= (1.f / 64.f);
    rs = rsqrtf(var + 1e-5f);
#pragma unroll
    for (int j = 0; j < 64; j++)
        x2[j] = (x2[j] - mu) * rs * __ldg(lg2 + j) + __ldg(lb2 + j);

    // ---- classifier + log_softmax ----
    u64 ca[8];
#pragma unroll
    for (int i = 0; i < 8; i++) ca[i] = pk(__ldg(bc + 2 * i), __ldg(bc + 2 * i + 1));
#pragma unroll 2
    for (int k = 0; k < 64; k++) {
        u64 xx = pk1(x2[k]);
        const float4* w = (const float4*)(Wc + k * 16);
        float4 w0 = __ldg(w), w1 = __ldg(w + 1), w2 = __ldg(w + 2), w3 = __ldg(w + 3);
        ca[0] = f2(xx, pk(w0.x, w0.y), ca[0]); ca[1] = f2(xx, pk(w0.z, w0.w), ca[1]);
        ca[2] = f2(xx, pk(w1.x, w1.y), ca[2]); ca[3] = f2(xx, pk(w1.z, w1.w), ca[3]);
        ca[4] = f2(xx, pk(w2.x, w2.y), ca[4]); ca[5] = f2(xx, pk(w2.z, w2.w), ca[5]);
        ca[6] = f2(xx, pk(w3.x, w3.y), ca[6]); ca[7] = f2(xx, pk(w3.z, w3.w), ca[7]);
    }
    float lg[16];
#pragma unroll
    for (int i = 0; i < 8; i++) upk(ca[i], lg[2 * i], lg[2 * i + 1]);
    float mx = lg[0];
#pragma unroll
    for (int c = 1; c < 16; c++) mx = fmaxf(mx, lg[c]);
    float ssum = 0.f;
#pragma unroll
    for (int c = 0; c < 16; c++) ssum += __expf(lg[c] - mx);
    float lse = mx + logf(ssum);
    float* orow = out + ((size_t)blockIdx.x * 256 + t) * 16;
#pragma unroll
    for (int j = 0; j < 4; j++)
        *(float4*)(orow + 4 * j) = make_float4(lg[4 * j] - lse, lg[4 * j + 1] - lse,
                                               lg[4 * j + 2] - lse, lg[4 * j + 3] - lse);
}

// =====================================================================
extern "C" void kernel_launch(void* const* d_in, const int* in_sizes, int n_in,
                              void* d_out, int out_size) {
    const float* x     = (const float*)d_in[0];
    const int*   Grows = (const int*)  d_in[1];
    const int*   Gcols = (const int*)  d_in[2];
    const float* Gvals = (const float*)d_in[3];
    const float* W1    = (const float*)d_in[4];
    const float* b1    = (const float*)d_in[5];
    const float* W2    = (const float*)d_in[6];
    const float* b2    = (const float*)d_in[7];
    const float* Wqkv  = (const float*)d_in[8];
    const float* bqkv  = (const float*)d_in[9];
    const float* Wo    = (const float*)d_in[10];
    const float* bo    = (const float*)d_in[11];
    const float* lg1   = (const float*)d_in[12];
    const float* lb1   = (const float*)d_in[13];
    const float* Wf1   = (const float*)d_in[14];
    const float* bf1   = (const float*)d_in[15];
    const float* Wf2   = (const float*)d_in[16];
    const float* bf2   = (const float*)d_in[17];
    const float* lg2   = (const float*)d_in[18];
    const float* lb2   = (const float*)d_in[19];
    const float* Wc    = (const float*)d_in[20];
    const float* bc    = (const float*)d_in[21];
    float* out = (float*)d_out;

    const int smem_k1  = 256 * 129 * 4;      // 132096
    const int smem_enc = 2 * 256 * SP * 4;   // 139264
    cudaFuncSetAttribute(k1_xw,  cudaFuncAttributeMaxDynamicSharedMemorySize, smem_k1);
    cudaFuncSetAttribute(k6_enc, cudaFuncAttributeMaxDynamicSharedMemorySize, smem_enc);

    float* gptr;
    float* xwptr;
    float* h1ptr;
    cudaGetSymbolAddress((void**)&gptr,  d_g);
    cudaGetSymbolAddress((void**)&xwptr, d_xw);
    cudaGetSymbolAddress((void**)&h1ptr, d_h1);

    k1_xw<<<512, 256, smem_k1>>>(x, W1);
    k_spmm<<<NNZV * 8 / 256, 256>>>((const float4*)xwptr, Grows, Gcols, Gvals, (float4*)gptr);
    k_relu<<<N_NODES * 32 / 1024, 256>>>(b1);
    k_spmm<<<NNZV * 8 / 256, 256>>>((const float4*)h1ptr, Grows, Gcols, Gvals, (float4*)gptr);
    k5_h2<<<512, 256>>>(W2, b2);
    k6_enc<<<512, 256, smem_enc>>>(Wqkv, bqkv, Wo, bo, lg1, lb1,
                                   Wf1, bf1, Wf2, bf2, lg2, lb2, Wc, bc, out);
}